// round 13
// baseline (speedup 1.0000x reference)
#include <cuda_runtime.h>
#include <cstdint>

// Problem constants
#define NN 20000          // nodes
#define NE 100000         // edges
#define HID 512
#define G3 1536           // 3*HID
#define NH 8              // heads
#define OD 64             // out dim per head

// ---------------- scratch (device globals; no allocation allowed) ----------
__device__ float    g_GI  [(size_t)NN * G3];   // per-node  x @ W_ih^T + b_ih
__device__ float    g_H1  [(size_t)NN * HID];  // per-node  h1
__device__ float    g_GH2 [(size_t)NN * G3];   // per-node  H1 @ W_hh^T + b_hh
__device__ float    g_h2  [(size_t)NE * HID];  // per-edge  h2
__device__ float    g_GH3 [(size_t)NE * G3];   // per-edge  h2 @ W_hh^T + b_hh
__device__ float    g_h3  [(size_t)NE * HID];  // per-edge  h3 (= eft)
__device__ float    g_a   [NE * NH];           // attention logits (post leaky)
__device__ float    g_ea  [NE * NH];           // exp(a - amax[dst])
__device__ unsigned g_amax[NN * NH];           // order-encoded float max
__device__ float    g_den [NN * NH];           // softmax denominators

// ---------------- helpers ---------------------------------------------------
__device__ __forceinline__ float sigmoidf(float x) { return 1.0f / (1.0f + expf(-x)); }

// order-preserving float<->uint encoding for atomicMax on floats
__device__ __forceinline__ unsigned f2o(float f) {
    unsigned u = __float_as_uint(f);
    return (u & 0x80000000u) ? ~u : (u | 0x80000000u);
}
__device__ __forceinline__ float o2f(unsigned u) {
    return __uint_as_float((u & 0x80000000u) ? (u ^ 0x80000000u) : ~u);
}

// ---------------- init: zero output / denom, set amax = enc(-inf) ----------
__global__ void init_kernel(float* __restrict__ out) {
    int i = blockIdx.x * blockDim.x + threadIdx.x;
    if (i < NN * HID) out[i] = 0.0f;
    if (i < NN * NH) { g_den[i] = 0.0f; g_amax[i] = 0x007FFFFFu; /* f2o(-inf) */ }
}

// ---------------- SGEMM: C[M,N] = A[M,K] @ B[N,K]^T + bias[N] --------------
// Tiles: BM=128, BN=128, BK=16. 256 threads, 8x8 per-thread microtile.
#define BM 128
#define BN 128
#define BK 16
__global__ __launch_bounds__(256)
void sgemm_bias(const float* __restrict__ A, int lda,
                const float* __restrict__ B,        // [N, K] row-major
                const float* __restrict__ bias,     // [N]
                float* __restrict__ C,              // [M, N]
                int M, int N, int K)
{
    __shared__ float As[BK][BM];
    __shared__ float Bs[BK][BN];

    const int tid = threadIdx.x;
    const int m0 = blockIdx.y * BM;
    const int n0 = blockIdx.x * BN;
    const int tx = tid & 15;     // 0..15 -> col microtile
    const int ty = tid >> 4;     // 0..15 -> row microtile

    const int lrow = tid >> 2;          // 0..63
    const int lcol = (tid & 3) << 2;    // 0,4,8,12

    float acc[8][8];
#pragma unroll
    for (int i = 0; i < 8; i++)
#pragma unroll
        for (int j = 0; j < 8; j++) acc[i][j] = 0.0f;

    for (int k0 = 0; k0 < K; k0 += BK) {
        // load A tile (rows m0+lrow, m0+lrow+64), cols k0+lcol..+3
#pragma unroll
        for (int rr = 0; rr < 2; rr++) {
            int r = lrow + rr * 64;
            int gm = m0 + r; if (gm >= M) gm = M - 1;   // clamp (store-guarded later)
            float4 v = *reinterpret_cast<const float4*>(&A[(size_t)gm * lda + k0 + lcol]);
            As[lcol + 0][r] = v.x; As[lcol + 1][r] = v.y;
            As[lcol + 2][r] = v.z; As[lcol + 3][r] = v.w;
        }
        // load B tile: Bs[k][n] = B[n0+n][k0+k]
#pragma unroll
        for (int rr = 0; rr < 2; rr++) {
            int n = lrow + rr * 64;
            float4 v = *reinterpret_cast<const float4*>(&B[(size_t)(n0 + n) * K + k0 + lcol]);
            Bs[lcol + 0][n] = v.x; Bs[lcol + 1][n] = v.y;
            Bs[lcol + 2][n] = v.z; Bs[lcol + 3][n] = v.w;
        }
        __syncthreads();

#pragma unroll
        for (int k = 0; k < BK; k++) {
            float4 a0 = *reinterpret_cast<const float4*>(&As[k][ty * 8]);
            float4 a1 = *reinterpret_cast<const float4*>(&As[k][ty * 8 + 4]);
            float4 b0 = *reinterpret_cast<const float4*>(&Bs[k][tx * 8]);
            float4 b1 = *reinterpret_cast<const float4*>(&Bs[k][tx * 8 + 4]);
            float af[8] = {a0.x, a0.y, a0.z, a0.w, a1.x, a1.y, a1.z, a1.w};
            float bf[8] = {b0.x, b0.y, b0.z, b0.w, b1.x, b1.y, b1.z, b1.w};
#pragma unroll
            for (int i = 0; i < 8; i++)
#pragma unroll
                for (int j = 0; j < 8; j++) acc[i][j] += af[i] * bf[j];
        }
        __syncthreads();
    }

    // epilogue: add bias, guarded store
    const int cn = n0 + tx * 8;
    float bv[8];
#pragma unroll
    for (int j = 0; j < 8; j++) bv[j] = bias[cn + j];
#pragma unroll
    for (int i = 0; i < 8; i++) {
        int gm = m0 + ty * 8 + i;
        if (gm < M) {
            float* cp = &C[(size_t)gm * N + cn];
#pragma unroll
            for (int j = 0; j < 8; j++) cp[j] = acc[i][j] + bv[j];
        }
    }
}

// ---------------- step 1 (per node): h1 from GI and b_hh --------------------
__global__ void h1_kernel(const float* __restrict__ b_hh) {
    int i = blockIdx.x * blockDim.x + threadIdx.x;
    if (i >= NN * HID) return;
    int n = i / HID, d = i % HID;
    const float* gi = g_GI + (size_t)n * G3;
    float r  = sigmoidf(gi[d]           + b_hh[d]);
    float z  = sigmoidf(gi[HID + d]     + b_hh[HID + d]);
    float nn = tanhf   (gi[2 * HID + d] + r * b_hh[2 * HID + d]);
    g_H1[(size_t)n * HID + d] = (1.0f - z) * nn;   // h0 = 0
}

// ---------------- step 2 (per edge): pure gather + elementwise --------------
__global__ void h2_kernel(const int* __restrict__ emi) {
    int e = blockIdx.x;
    int d = threadIdx.x;
    int i0 = emi[e * 3 + 0];
    int i1 = emi[e * 3 + 1];
    const float* gi = g_GI  + (size_t)i1 * G3;
    const float* gh = g_GH2 + (size_t)i0 * G3;
    float r  = sigmoidf(gi[d]           + gh[d]);
    float z  = sigmoidf(gi[HID + d]     + gh[HID + d]);
    float nn = tanhf   (gi[2 * HID + d] + r * gh[2 * HID + d]);
    float hp = g_H1[(size_t)i0 * HID + d];
    g_h2[(size_t)e * HID + d] = (1.0f - z) * nn + z * hp;
}

// ---------------- step 3 (per edge): GI gather + per-edge gh ----------------
__global__ void h3_kernel(const int* __restrict__ emi) {
    int e = blockIdx.x;
    int d = threadIdx.x;
    int i2 = emi[e * 3 + 2];
    const float* gi = g_GI  + (size_t)i2 * G3;
    const float* gh = g_GH3 + (size_t)e  * G3;
    float r  = sigmoidf(gi[d]           + gh[d]);
    float z  = sigmoidf(gi[HID + d]     + gh[HID + d]);
    float nn = tanhf   (gi[2 * HID + d] + r * gh[2 * HID + d]);
    float hp = g_h2[(size_t)e * HID + d];
    g_h3[(size_t)e * HID + d] = (1.0f - z) * nn + z * hp;
}

// ---------------- attention logits + segment max -----------------------------
// one block per edge, 8 warps = 8 heads; warp reduces a 64-wide dot.
__global__ void attn_kernel(const float* __restrict__ attn,
                            const int* __restrict__ edge_dst) {
    int e = blockIdx.x;
    int w = threadIdx.x >> 5;
    int lane = threadIdx.x & 31;
    const float* h3 = g_h3 + (size_t)e * HID + w * OD;
    float v = h3[lane]      * attn[w * OD + lane]
            + h3[lane + 32] * attn[w * OD + lane + 32];
#pragma unroll
    for (int o = 16; o > 0; o >>= 1) v += __shfl_xor_sync(0xffffffffu, v, o);
    if (lane == 0) {
        float a = (v >= 0.0f) ? v : 0.01f * v;   // leaky relu
        g_a[e * NH + w] = a;
        int dst = edge_dst[e];
        atomicMax(&g_amax[dst * NH + w], f2o(a));
    }
}

// ---------------- exp + segment sum ------------------------------------------
__global__ void expsum_kernel(const int* __restrict__ edge_dst) {
    int i = blockIdx.x * blockDim.x + threadIdx.x;
    if (i >= NE * NH) return;
    int e = i >> 3, h = i & 7;
    int dst = edge_dst[e];
    float m = o2f(g_amax[dst * NH + h]);
    float ea = expf(g_a[i] - m);
    g_ea[i] = ea;
    atomicAdd(&g_den[dst * NH + h], ea);
}

// ---------------- weighted aggregation to destination nodes -----------------
__global__ void agg_kernel(const int* __restrict__ edge_dst,
                           float* __restrict__ out) {
    int e = blockIdx.x;
    int j = threadIdx.x;          // j = h*64 + d
    int h = j >> 6;
    int dst = edge_dst[e];
    float alpha = g_ea[e * NH + h] / g_den[dst * NH + h];
    atomicAdd(&out[(size_t)dst * HID + j], g_h3[(size_t)e * HID + j] * alpha);
}

// ---------------- launcher ----------------------------------------------------
extern "C" void kernel_launch(void* const* d_in, const int* in_sizes, int n_in,
                              void* d_out, int out_size) {
    const float* features = (const float*)d_in[0];   // [20000, 64]
    const float* W_ih     = (const float*)d_in[1];   // [1536, 64]
    const float* W_hh     = (const float*)d_in[2];   // [1536, 512]
    const float* b_ih     = (const float*)d_in[3];   // [1536]
    const float* b_hh     = (const float*)d_in[4];   // [1536]
    const float* attn     = (const float*)d_in[5];   // [8, 64]
    const int*   emi      = (const int*)  d_in[6];   // [100000, 3]
    const int*   edge_dst = (const int*)  d_in[7];   // [100000]
    float* out = (float*)d_out;                      // [20000, 8, 64]

    float *GI, *H1, *GH2, *h2, *GH3;
    cudaGetSymbolAddress((void**)&GI,  g_GI);
    cudaGetSymbolAddress((void**)&H1,  g_H1);
    cudaGetSymbolAddress((void**)&GH2, g_GH2);
    cudaGetSymbolAddress((void**)&h2,  g_h2);
    cudaGetSymbolAddress((void**)&GH3, g_GH3);

    // 0. init output / softmax accumulators
    init_kernel<<<(NN * HID + 255) / 256, 256>>>(out);

    // 1. GI = features @ W_ih^T + b_ih     (per node)
    dim3 gN(G3 / BN, (NN + BM - 1) / BM);
    sgemm_bias<<<gN, 256>>>(features, OD, W_ih, b_ih, GI, NN, G3, OD);

    // 2. H1 per node (elementwise)
    h1_kernel<<<(NN * HID + 255) / 256, 256>>>(b_hh);

    // 3. GH2 = H1 @ W_hh^T + b_hh          (per node)
    sgemm_bias<<<gN, 256>>>(H1, HID, W_hh, b_hh, GH2, NN, G3, HID);

    // 4. h2 per edge (pure gather + elementwise)
    h2_kernel<<<NE, HID>>>(emi);

    // 5. GH3 = h2 @ W_hh^T + b_hh          (per edge — the only big GEMM)
    dim3 gE(G3 / BN, (NE + BM - 1) / BM);
    sgemm_bias<<<gE, 256>>>(h2, HID, W_hh, b_hh, GH3, NE, G3, HID);

    // 6. h3 per edge
    h3_kernel<<<NE, HID>>>(emi);

    // 7-9. attention logits -> edge softmax by dst -> weighted segment sum
    attn_kernel<<<NE, 256>>>(attn, edge_dst);
    expsum_kernel<<<(NE * NH + 255) / 256, 256>>>(edge_dst);
    agg_kernel<<<NE, HID>>>(edge_dst, out);
}

// round 14
// speedup vs baseline: 2.0488x; 2.0488x over previous
#include <cuda_runtime.h>
#include <cstdint>

// Problem constants
#define NN 20000          // nodes
#define NE 100000         // edges
#define HID 512
#define G3 1536           // 3*HID
#define NH 8              // heads
#define OD 64             // out dim per head

// ---------------- scratch (device globals; no allocation allowed) ----------
__device__ float    g_GI  [(size_t)NN * G3];   // per-node  x @ W_ih^T + b_ih
__device__ float    g_H1  [(size_t)NN * HID];  // per-node  h1
__device__ float    g_GH2 [(size_t)NN * G3];   // per-node  H1 @ W_hh^T + b_hh
__device__ float    g_h2  [(size_t)NE * HID];  // per-edge  h2
__device__ float    g_GH3 [(size_t)NE * G3];   // per-edge  h2 @ W_hh^T + b_hh
__device__ float    g_h3  [(size_t)NE * HID];  // per-edge  h3 (= eft)
__device__ float    g_a   [NE * NH];           // attention logits (post leaky)
__device__ float    g_ea  [NE * NH];           // exp(a - amax[dst])
__device__ unsigned g_amax[NN * NH];           // order-encoded float max
__device__ float    g_den [NN * NH];           // softmax denominators

// ---------------- helpers ---------------------------------------------------
__device__ __forceinline__ float sigmoidf(float x) { return 1.0f / (1.0f + expf(-x)); }

__device__ __forceinline__ unsigned f2o(float f) {
    unsigned u = __float_as_uint(f);
    return (u & 0x80000000u) ? ~u : (u | 0x80000000u);
}
__device__ __forceinline__ float o2f(unsigned u) {
    return __uint_as_float((u & 0x80000000u) ? (u ^ 0x80000000u) : ~u);
}

__device__ __forceinline__ uint32_t f2tf32(float f) {
    uint32_t r;
    asm("cvt.rna.tf32.f32 %0, %1;" : "=r"(r) : "f"(f));
    return r;
}

__device__ __forceinline__ void mma_tf32(float c[4],
                                         uint32_t a0, uint32_t a1, uint32_t a2, uint32_t a3,
                                         uint32_t b0, uint32_t b1) {
    asm volatile(
        "mma.sync.aligned.m16n8k8.row.col.f32.tf32.tf32.f32 "
        "{%0,%1,%2,%3}, {%4,%5,%6,%7}, {%8,%9}, {%0,%1,%2,%3};"
        : "+f"(c[0]), "+f"(c[1]), "+f"(c[2]), "+f"(c[3])
        : "r"(a0), "r"(a1), "r"(a2), "r"(a3), "r"(b0), "r"(b1));
}

// ---------------- init: zero output / denom, set amax = enc(-inf) ----------
__global__ void init_kernel(float* __restrict__ out) {
    int i = blockIdx.x * blockDim.x + threadIdx.x;
    if (i < NN * HID) out[i] = 0.0f;
    if (i < NN * NH) { g_den[i] = 0.0f; g_amax[i] = 0x007FFFFFu; /* f2o(-inf) */ }
}

// ---------------- TF32 tensor-core GEMM: C = A[M,K] @ B[N,K]^T + bias[N] ----
// Block tile 128x128, BK=16, 8 warps (2x4) of 64x32 warp tiles.
// mma.sync.m16n8k8 tf32, fp32 accumulate. A,B row-major (B's rows are the
// "col" operand layout required by m16n8k8.row.col).
#define BM 128
#define BN 128
#define BK 16
#define SKEW 4

__global__ __launch_bounds__(256)
void tc_gemm_bias(const float* __restrict__ A, int lda,
                  const float* __restrict__ B,        // [N, K] row-major
                  const float* __restrict__ bias,     // [N]
                  float* __restrict__ C,              // [M, N]
                  int M, int N, int K)
{
    __shared__ __align__(16) uint32_t As[2][BM][BK + SKEW];
    __shared__ __align__(16) uint32_t Bs[2][BN][BK + SKEW];

    const int tid  = threadIdx.x;
    const int lane = tid & 31;
    const int warp = tid >> 5;
    const int wm = (warp >> 2) * 64;   // warp row offset within block tile
    const int wn = (warp & 3) * 32;    // warp col offset
    const int m0 = blockIdx.y * BM;
    const int n0 = blockIdx.x * BN;

    float acc[4][4][4];
#pragma unroll
    for (int mi = 0; mi < 4; mi++)
#pragma unroll
        for (int ni = 0; ni < 4; ni++)
#pragma unroll
            for (int r = 0; r < 4; r++) acc[mi][ni][r] = 0.0f;

    // global->reg staging: each thread loads 2 float4 for A and 2 for B
    const int lr  = tid >> 2;            // 0..63 (rows lr and lr+64)
    const int lc4 = (tid & 3) * 4;       // col offset within BK: 0,4,8,12
    int gmA0 = m0 + lr;       if (gmA0 >= M) gmA0 = M - 1;   // clamp; stores guarded
    int gmA1 = m0 + lr + 64;  if (gmA1 >= M) gmA1 = M - 1;
    const int gnB0 = n0 + lr;            // N is a multiple of 128 here
    const int gnB1 = n0 + lr + 64;

    float4 pa0, pa1, pb0, pb1;

    const int kt = K / BK;

#define GLOAD(k0)                                                              \
    do {                                                                       \
        pa0 = *reinterpret_cast<const float4*>(&A[(size_t)gmA0 * lda + (k0) + lc4]); \
        pa1 = *reinterpret_cast<const float4*>(&A[(size_t)gmA1 * lda + (k0) + lc4]); \
        pb0 = *reinterpret_cast<const float4*>(&B[(size_t)gnB0 * K   + (k0) + lc4]); \
        pb1 = *reinterpret_cast<const float4*>(&B[(size_t)gnB1 * K   + (k0) + lc4]); \
    } while (0)

#define STS(buf)                                                               \
    do {                                                                       \
        uint4 u;                                                               \
        u.x = f2tf32(pa0.x); u.y = f2tf32(pa0.y); u.z = f2tf32(pa0.z); u.w = f2tf32(pa0.w); \
        *reinterpret_cast<uint4*>(&As[buf][lr][lc4]) = u;                      \
        u.x = f2tf32(pa1.x); u.y = f2tf32(pa1.y); u.z = f2tf32(pa1.z); u.w = f2tf32(pa1.w); \
        *reinterpret_cast<uint4*>(&As[buf][lr + 64][lc4]) = u;                 \
        u.x = f2tf32(pb0.x); u.y = f2tf32(pb0.y); u.z = f2tf32(pb0.z); u.w = f2tf32(pb0.w); \
        *reinterpret_cast<uint4*>(&Bs[buf][lr][lc4]) = u;                      \
        u.x = f2tf32(pb1.x); u.y = f2tf32(pb1.y); u.z = f2tf32(pb1.z); u.w = f2tf32(pb1.w); \
        *reinterpret_cast<uint4*>(&Bs[buf][lr + 64][lc4]) = u;                 \
    } while (0)

    GLOAD(0);
    STS(0);
    __syncthreads();

    const int gq = lane >> 2;   // group id 0..7
    const int gc = lane & 3;    // thread-in-group 0..3

#pragma unroll 1
    for (int t = 0; t < kt; t++) {
        if (t + 1 < kt) GLOAD((t + 1) * BK);

        const int buf = t & 1;
#pragma unroll
        for (int kk = 0; kk < 2; kk++) {
            const int kc = kk * 8 + gc;
            uint32_t af[4][4], bf[4][2];
#pragma unroll
            for (int mi = 0; mi < 4; mi++) {
                const int r = wm + mi * 16 + gq;
                af[mi][0] = As[buf][r][kc];
                af[mi][1] = As[buf][r + 8][kc];
                af[mi][2] = As[buf][r][kc + 4];
                af[mi][3] = As[buf][r + 8][kc + 4];
            }
#pragma unroll
            for (int ni = 0; ni < 4; ni++) {
                const int r = wn + ni * 8 + gq;
                bf[ni][0] = Bs[buf][r][kc];
                bf[ni][1] = Bs[buf][r][kc + 4];
            }
#pragma unroll
            for (int mi = 0; mi < 4; mi++)
#pragma unroll
                for (int ni = 0; ni < 4; ni++)
                    mma_tf32(acc[mi][ni],
                             af[mi][0], af[mi][1], af[mi][2], af[mi][3],
                             bf[ni][0], bf[ni][1]);
        }

        if (t + 1 < kt) {
            STS((t + 1) & 1);
            __syncthreads();
        }
    }

    // epilogue: add bias, guarded float2 stores
#pragma unroll
    for (int mi = 0; mi < 4; mi++) {
        const int r = m0 + wm + mi * 16 + gq;
#pragma unroll
        for (int ni = 0; ni < 4; ni++) {
            const int c = n0 + wn + ni * 8 + gc * 2;
            const float b0 = bias[c], b1 = bias[c + 1];
            if (r < M)
                *reinterpret_cast<float2*>(&C[(size_t)r * N + c]) =
                    make_float2(acc[mi][ni][0] + b0, acc[mi][ni][1] + b1);
            if (r + 8 < M)
                *reinterpret_cast<float2*>(&C[(size_t)(r + 8) * N + c]) =
                    make_float2(acc[mi][ni][2] + b0, acc[mi][ni][3] + b1);
        }
    }
#undef GLOAD
#undef STS
}

// ---------------- step 1 (per node): h1 from GI and b_hh --------------------
__global__ void h1_kernel(const float* __restrict__ b_hh) {
    int i = blockIdx.x * blockDim.x + threadIdx.x;
    if (i >= NN * HID) return;
    int n = i / HID, d = i % HID;
    const float* gi = g_GI + (size_t)n * G3;
    float r  = sigmoidf(gi[d]           + b_hh[d]);
    float z  = sigmoidf(gi[HID + d]     + b_hh[HID + d]);
    float nn = tanhf   (gi[2 * HID + d] + r * b_hh[2 * HID + d]);
    g_H1[(size_t)n * HID + d] = (1.0f - z) * nn;   // h0 = 0
}

// ---------------- step 2 (per edge): pure gather + elementwise --------------
__global__ void h2_kernel(const int* __restrict__ emi) {
    int e = blockIdx.x;
    int d = threadIdx.x;
    int i0 = emi[e * 3 + 0];
    int i1 = emi[e * 3 + 1];
    const float* gi = g_GI  + (size_t)i1 * G3;
    const float* gh = g_GH2 + (size_t)i0 * G3;
    float r  = sigmoidf(gi[d]           + gh[d]);
    float z  = sigmoidf(gi[HID + d]     + gh[HID + d]);
    float nn = tanhf   (gi[2 * HID + d] + r * gh[2 * HID + d]);
    float hp = g_H1[(size_t)i0 * HID + d];
    g_h2[(size_t)e * HID + d] = (1.0f - z) * nn + z * hp;
}

// ---------------- step 3 (per edge): GI gather + per-edge gh ----------------
__global__ void h3_kernel(const int* __restrict__ emi) {
    int e = blockIdx.x;
    int d = threadIdx.x;
    int i2 = emi[e * 3 + 2];
    const float* gi = g_GI  + (size_t)i2 * G3;
    const float* gh = g_GH3 + (size_t)e  * G3;
    float r  = sigmoidf(gi[d]           + gh[d]);
    float z  = sigmoidf(gi[HID + d]     + gh[HID + d]);
    float nn = tanhf   (gi[2 * HID + d] + r * gh[2 * HID + d]);
    float hp = g_h2[(size_t)e * HID + d];
    g_h3[(size_t)e * HID + d] = (1.0f - z) * nn + z * hp;
}

// ---------------- attention logits + segment max -----------------------------
__global__ void attn_kernel(const float* __restrict__ attn,
                            const int* __restrict__ edge_dst) {
    int e = blockIdx.x;
    int w = threadIdx.x >> 5;
    int lane = threadIdx.x & 31;
    const float* h3 = g_h3 + (size_t)e * HID + w * OD;
    float v = h3[lane]      * attn[w * OD + lane]
            + h3[lane + 32] * attn[w * OD + lane + 32];
#pragma unroll
    for (int o = 16; o > 0; o >>= 1) v += __shfl_xor_sync(0xffffffffu, v, o);
    if (lane == 0) {
        float a = (v >= 0.0f) ? v : 0.01f * v;   // leaky relu
        g_a[e * NH + w] = a;
        int dst = edge_dst[e];
        atomicMax(&g_amax[dst * NH + w], f2o(a));
    }
}

// ---------------- exp + segment sum ------------------------------------------
__global__ void expsum_kernel(const int* __restrict__ edge_dst) {
    int i = blockIdx.x * blockDim.x + threadIdx.x;
    if (i >= NE * NH) return;
    int e = i >> 3, h = i & 7;
    int dst = edge_dst[e];
    float m = o2f(g_amax[dst * NH + h]);
    float ea = expf(g_a[i] - m);
    g_ea[i] = ea;
    atomicAdd(&g_den[dst * NH + h], ea);
}

// ---------------- weighted aggregation to destination nodes -----------------
__global__ void agg_kernel(const int* __restrict__ edge_dst,
                           float* __restrict__ out) {
    int e = blockIdx.x;
    int j = threadIdx.x;          // j = h*64 + d
    int h = j >> 6;
    int dst = edge_dst[e];
    float alpha = g_ea[e * NH + h] / g_den[dst * NH + h];
    atomicAdd(&out[(size_t)dst * HID + j], g_h3[(size_t)e * HID + j] * alpha);
}

// ---------------- launcher ----------------------------------------------------
extern "C" void kernel_launch(void* const* d_in, const int* in_sizes, int n_in,
                              void* d_out, int out_size) {
    const float* features = (const float*)d_in[0];   // [20000, 64]
    const float* W_ih     = (const float*)d_in[1];   // [1536, 64]
    const float* W_hh     = (const float*)d_in[2];   // [1536, 512]
    const float* b_ih     = (const float*)d_in[3];   // [1536]
    const float* b_hh     = (const float*)d_in[4];   // [1536]
    const float* attn     = (const float*)d_in[5];   // [8, 64]
    const int*   emi      = (const int*)  d_in[6];   // [100000, 3]
    const int*   edge_dst = (const int*)  d_in[7];   // [100000]
    float* out = (float*)d_out;                      // [20000, 8, 64]

    float *GI, *H1, *GH2, *h2, *GH3;
    cudaGetSymbolAddress((void**)&GI,  g_GI);
    cudaGetSymbolAddress((void**)&H1,  g_H1);
    cudaGetSymbolAddress((void**)&GH2, g_GH2);
    cudaGetSymbolAddress((void**)&h2,  g_h2);
    cudaGetSymbolAddress((void**)&GH3, g_GH3);

    // 0. init output / softmax accumulators
    init_kernel<<<(NN * HID + 255) / 256, 256>>>(out);

    // 1. GI = features @ W_ih^T + b_ih     (per node, K=64)
    dim3 gN(G3 / BN, (NN + BM - 1) / BM);
    tc_gemm_bias<<<gN, 256>>>(features, OD, W_ih, b_ih, GI, NN, G3, OD);

    // 2. H1 per node (elementwise)
    h1_kernel<<<(NN * HID + 255) / 256, 256>>>(b_hh);

    // 3. GH2 = H1 @ W_hh^T + b_hh          (per node, K=512)
    tc_gemm_bias<<<gN, 256>>>(H1, HID, W_hh, b_hh, GH2, NN, G3, HID);

    // 4. h2 per edge (pure gather + elementwise)
    h2_kernel<<<NE, HID>>>(emi);

    // 5. GH3 = h2 @ W_hh^T + b_hh          (per edge — the only big GEMM)
    dim3 gE(G3 / BN, (NE + BM - 1) / BM);
    tc_gemm_bias<<<gE, 256>>>(h2, HID, W_hh, b_hh, GH3, NE, G3, HID);

    // 6. h3 per edge
    h3_kernel<<<NE, HID>>>(emi);

    // 7-9. attention logits -> edge softmax by dst -> weighted segment sum
    attn_kernel<<<NE, 256>>>(attn, edge_dst);
    expsum_kernel<<<(NE * NH + 255) / 256, 256>>>(edge_dst);
    agg_kernel<<<NE, HID>>>(edge_dst, out);
}